// round 2
// baseline (speedup 1.0000x reference)
#include <cuda_runtime.h>
#include <cuda_bf16.h>
#include <cstdint>

// Problem constants (fixed by the dataset)
#define B_   32
#define T_   256
#define M_   (B_ * T_)     // 8192
#define E_   512
#define H_   512
#define K0_  512           // layer 0 K
#define K1_  1024          // layer 1 K

// Tile config
#define BM 64
#define BH 32
#define BK 16

// Output layout in d_out (float32), concatenated in reference return order:
//   [0, 32768)                    h_last  (L=2, B=32, H=512)
//   [32768, 65536)                c_last  (L=2, B=32, H=512)
//   [65536, 65536+8388608)        encoder_out (B=32, T=256, L=2, H=512)
#define OUT_C_OFF   (2 * B_ * H_)
#define OUT_ENC_OFF (4 * B_ * H_)

// Scratch: layer-0 output, (M, 2H) = h_fwd | h_bwd per row. 33.5 MB.
__device__ float g_inp1[(size_t)M_ * (2 * H_)];

__device__ __forceinline__ float sigm(float x) {
    return 1.0f / (1.0f + __expf(-x));
}

// One fused layer: gather(optional) -> GEMM over 6 gate tiles (i,g,o x 2 dirs)
// -> activations -> writes.
// GEMM: out[m, gate_row] = sum_k A[m,k] * W[d][gate_row][k]
// gate rows used: i -> [0,H), g -> [2H,3H), o -> [3H,4H)   (f skipped: c0 = 0)
template <int K, bool GATHER, int LAYER>
__global__ __launch_bounds__(256)
void lstm_layer_kernel(const int* __restrict__ x,
                       const float* __restrict__ emb,
                       const float* __restrict__ W,    // (2, 4H, K)
                       const float* __restrict__ bi,   // (2, 4H)
                       const float* __restrict__ bh,   // (2, 4H)
                       float* __restrict__ out)
{
    __shared__ float As[BK][BM + 4];        // [k][m], padded vs conflicts
    __shared__ float Ws[6][BK][BH];         // [gate(d*3+s)][k][c]
    __shared__ const float* Arow[BM];

    const int bm  = blockIdx.x;             // M tile
    const int bhx = blockIdx.y;             // H tile
    const int tid = threadIdx.x;
    const int tx  = tid & 15;               // 0..15 -> 2 cols each
    const int ty  = tid >> 4;               // 0..15 -> 4 rows each

    // Per-row source pointers (embedding gather for layer 0, dense for layer 1)
    if (tid < BM) {
        const int m = bm * BM + tid;
        if (GATHER) {
            Arow[tid] = emb + (size_t)x[m] * K;
        } else {
            Arow[tid] = &g_inp1[(size_t)m * K];
        }
    }
    __syncthreads();

    float acc[6][4][2];
    #pragma unroll
    for (int g = 0; g < 6; g++)
        #pragma unroll
        for (int i = 0; i < 4; i++) { acc[g][i][0] = 0.f; acc[g][i][1] = 0.f; }

    const int col0 = bhx * BH;   // h-column base of this tile

    for (int k0 = 0; k0 < K; k0 += BK) {
        // ---- load A tile: 64 rows x 16 k (one float4 per thread) ----
        {
            const int r  = tid >> 2;
            const int kk = (tid & 3) * 4;
            const float4 v = *(const float4*)(Arow[r] + k0 + kk);
            As[kk + 0][r] = v.x; As[kk + 1][r] = v.y;
            As[kk + 2][r] = v.z; As[kk + 3][r] = v.w;
        }
        // ---- load 6 W tiles: 6 x 32 cols x 16 k (3 float4 per thread) ----
        #pragma unroll
        for (int j = 0; j < 3; j++) {
            const int u  = tid + 256 * j;       // 0..767
            const int gg = u >> 7;              // 0..5
            const int v  = u & 127;
            const int c  = v >> 2;              // 0..31
            const int kk = (v & 3) * 4;
            const int d  = (gg >= 3) ? 1 : 0;
            const int s  = gg - d * 3;          // 0=i,1=g,2=o
            const int rowbase = (s == 0) ? 0 : (s == 1 ? 2 * H_ : 3 * H_);
            const int row = rowbase + col0 + c;
            const float4 w4 = *(const float4*)(W + ((size_t)d * (4 * H_) + row) * K + k0 + kk);
            Ws[gg][kk + 0][c] = w4.x; Ws[gg][kk + 1][c] = w4.y;
            Ws[gg][kk + 2][c] = w4.z; Ws[gg][kk + 3][c] = w4.w;
        }
        __syncthreads();

        // ---- inner product ----
        #pragma unroll
        for (int kk = 0; kk < BK; kk++) {
            float a[4];
            #pragma unroll
            for (int i = 0; i < 4; i++) a[i] = As[kk][ty * 4 + i];
            #pragma unroll
            for (int gg = 0; gg < 6; gg++) {
                const float2 w = *(const float2*)&Ws[gg][kk][tx * 2];
                #pragma unroll
                for (int i = 0; i < 4; i++) {
                    acc[gg][i][0] = fmaf(a[i], w.x, acc[gg][i][0]);
                    acc[gg][i][1] = fmaf(a[i], w.y, acc[gg][i][1]);
                }
            }
        }
        __syncthreads();
    }

    // ---- epilogue: biases + activations + writes ----
    // bias per gate column: bi[d][row] + bh[d][row]
    float bias[6][2];
    #pragma unroll
    for (int gg = 0; gg < 6; gg++) {
        const int d = (gg >= 3) ? 1 : 0;
        const int s = gg - d * 3;
        const int rowbase = (s == 0) ? 0 : (s == 1 ? 2 * H_ : 3 * H_);
        #pragma unroll
        for (int j = 0; j < 2; j++) {
            const int row = rowbase + col0 + tx * 2 + j;
            bias[gg][j] = bi[d * (4 * H_) + row] + bh[d * (4 * H_) + row];
        }
    }

    const int m0 = bm * BM;
    #pragma unroll
    for (int i = 0; i < 4; i++) {
        const int m = m0 + ty * 4 + i;
        const int b = m >> 8;         // m / T_
        const int t = m & (T_ - 1);
        #pragma unroll
        for (int j = 0; j < 2; j++) {
            const int ncol = col0 + tx * 2 + j;
            float hv[2], cv[2];
            #pragma unroll
            for (int d = 0; d < 2; d++) {
                const float zi = acc[d * 3 + 0][i][j] + bias[d * 3 + 0][j];
                const float zg = acc[d * 3 + 1][i][j] + bias[d * 3 + 1][j];
                const float zo = acc[d * 3 + 2][i][j] + bias[d * 3 + 2][j];
                const float cc = sigm(zi) * tanhf(zg);
                const float hh = sigm(zo) * tanhf(cc);
                cv[d] = cc;
                hv[d] = hh;
            }
            if (LAYER == 0) {
                g_inp1[(size_t)m * (2 * H_) + ncol]        = hv[0];
                g_inp1[(size_t)m * (2 * H_) + H_ + ncol]   = hv[1];
            }
            // encoder_out[b][t][LAYER][ncol] = hf + hb
            out[OUT_ENC_OFF + ((size_t)m * 2 + LAYER) * H_ + ncol] = hv[0] + hv[1];
            if (t == T_ - 1) {
                // forward-direction h_n / c_n at last timestep
                out[(LAYER * B_ + b) * H_ + ncol]               = hv[0];
                out[OUT_C_OFF + (LAYER * B_ + b) * H_ + ncol]   = cv[0];
            }
        }
    }
}

extern "C" void kernel_launch(void* const* d_in, const int* in_sizes, int n_in,
                              void* d_out, int out_size)
{
    const int*   x    = (const int*)  d_in[0];
    const float* emb  = (const float*)d_in[1];
    const float* W0   = (const float*)d_in[2];   // W_ih_l0 (2, 2048, 512)
    // d_in[3] = W_hh_l0 : unused (h0 == 0)
    const float* bi0  = (const float*)d_in[4];
    const float* bh0  = (const float*)d_in[5];
    const float* W1   = (const float*)d_in[6];   // W_ih_l1 (2, 2048, 1024)
    // d_in[7] = W_hh_l1 : unused
    const float* bi1  = (const float*)d_in[8];
    const float* bh1  = (const float*)d_in[9];
    float* out = (float*)d_out;

    dim3 grid(M_ / BM, H_ / BH);
    lstm_layer_kernel<K0_, true, 0><<<grid, 256>>>(x, emb, W0, bi0, bh0, out);
    lstm_layer_kernel<K1_, false, 1><<<grid, 256>>>(nullptr, nullptr, W1, bi1, bh1, out);
}

// round 6
// speedup vs baseline: 3.2214x; 3.2214x over previous
#include <cuda_runtime.h>
#include <cstdint>

// ---------------- problem constants ----------------
#define OUT_C_OFF   (2 * 32 * 512)
#define OUT_ENC_OFF (4 * 32 * 512)

// ---------------- device scratch (no allocs allowed) ----------------
// All GEMM operands are rna-rounded to tf32 and k-permuted ([0,4,1,5,2,6,3,7]
// within each 8-column group) so fragment pairs (k, k+4) are contiguous.
__device__ float g_a0[(size_t)8192 * 512];    // gathered embeddings
__device__ float g_w0[(size_t)3072 * 512];    // L0 weights, gate-major rows: i_f,g_f,o_f,i_b,g_b,o_b
__device__ float g_w1[(size_t)3072 * 1024];   // L1 weights, gate-major rows
__device__ float g_inp1[(size_t)8192 * 1024]; // L0 output h (rounded, permuted): [h_f | h_b]
__device__ float g_b0[3072];                  // combined biases, gate-major
__device__ float g_b1[3072];

// ---------------- helpers ----------------
__device__ __forceinline__ float tf32r(float f) {
    uint32_t u; asm("cvt.rna.tf32.f32 %0, %1;" : "=r"(u) : "f"(f));
    return __uint_as_float(u);
}
__device__ __forceinline__ float tanh_ap(float x) {
    float r; asm("tanh.approx.f32 %0, %1;" : "=f"(r) : "f"(x)); return r;
}
__device__ __forceinline__ float sigm(float x) { return 0.5f * tanh_ap(0.5f * x) + 0.5f; }

__device__ __forceinline__ uint32_t s2u(const void* p) {
    uint32_t a;
    asm("{ .reg .u64 t; cvta.to.shared.u64 t, %1; cvt.u32.u64 %0, t; }" : "=r"(a) : "l"(p));
    return a;
}
__device__ __forceinline__ void cp16(uint32_t d, const void* s) {
    asm volatile("cp.async.cg.shared.global [%0], [%1], 16;" :: "r"(d), "l"(s));
}

// k-permutation: logical column L -> stored slot
__device__ __forceinline__ int kslot(int L) {
    return (L & ~7) + ((L & 3) << 1) + ((L >> 2) & 1);
}

// m16n8k8 tf32 HMMA: D += A * B,  A row-major frag, B col-major frag
__device__ __forceinline__ void mma8(float* d, float2 al, float2 ah, float2 b) {
    asm volatile(
        "mma.sync.aligned.m16n8k8.row.col.f32.tf32.tf32.f32 "
        "{%0,%1,%2,%3},{%4,%5,%6,%7},{%8,%9},{%0,%1,%2,%3};"
        : "+f"(d[0]), "+f"(d[1]), "+f"(d[2]), "+f"(d[3])
        : "r"(__float_as_uint(al.x)), "r"(__float_as_uint(ah.x)),
          "r"(__float_as_uint(al.y)), "r"(__float_as_uint(ah.y)),
          "r"(__float_as_uint(b.x)),  "r"(__float_as_uint(b.y)));
}

// ---------------- stage loader (cp.async, double buffer) ----------------
// smem: A tile 128 rows x 32 k, row stride 40 floats (160B); B tile 192 x 32, stride 40.
template <int K>
__device__ __forceinline__ void stage_load(uint32_t sAu, uint32_t sBu,
                                           const float* __restrict__ A,
                                           const float* __restrict__ W,
                                           int m0, int c0, int s, int tid) {
    const int k0 = s * 32;
    const int b  = s & 1;
    // A: 128 rows x 8 chunks(16B); 2 threads/row, 4 chunks each
    const int ar = tid >> 1, ac0 = (tid & 1) * 4;
    const float* asrc = A + (size_t)(m0 + ar) * K + k0;
    const uint32_t ad = sAu + b * 20480 + ar * 160;
    #pragma unroll
    for (int i = 0; i < 4; i++) cp16(ad + (ac0 + i) * 16, asrc + (ac0 + i) * 4);
    // B: 192 rows x 8 chunks; 6 chunks per thread
    #pragma unroll
    for (int i = 0; i < 6; i++) {
        const int u = tid + 256 * i;
        const int r = u >> 3, ch = u & 7;
        const float* wsrc = W + (size_t)((r >> 5) * 512 + c0 + (r & 31)) * K + k0 + ch * 4;
        cp16(sBu + b * 30720 + r * 160 + ch * 16, wsrc);
    }
    asm volatile("cp.async.commit_group;" ::: "memory");
}

// ---------------- fused LSTM layer (mma.sync tf32) ----------------
// CTA: 128 m-rows x 32 h-cols, 6 gate blocks (N_eff = 192). 8 warps = 4(m) x 2(n).
template <int K, int LAYER>
__global__ void __launch_bounds__(256, 1)
lstm_mma(float* __restrict__ out)
{
    constexpr int S = K / 32;
    extern __shared__ float sm[];
    float* sA = sm;                 // 2 * 128 * 40 = 10240 floats
    float* sB = sm + 10240;         // 2 * 192 * 40 = 15360 floats
    float* sbias = sm + 25600;      // 192 floats

    const float* A  = LAYER ? g_inp1 : g_a0;
    const float* W  = LAYER ? g_w1   : g_w0;
    const float* bv = LAYER ? g_b1   : g_b0;

    const int tid = threadIdx.x, lane = tid & 31, w = tid >> 5;
    const int wm = w & 3, wn = w >> 2;
    const int m0 = blockIdx.x * 128, c0 = blockIdx.y * 32;

    if (tid < 192) sbias[tid] = bv[(tid >> 5) * 512 + c0 + (tid & 31)];

    const uint32_t sAu = s2u(sA), sBu = s2u(sB);

    float acc0[12][4] = {}, acc1[12][4] = {};   // [gate*2+q][c]  for m-tiles 0/1

    stage_load<K>(sAu, sBu, A, W, m0, c0, 0, tid);
    stage_load<K>(sAu, sBu, A, W, m0, c0, 1, tid);

    const float* aB = sA + (wm * 32 + (lane >> 2)) * 40 + 2 * (lane & 3);
    const float* bB = sB + (wn * 16 + (lane >> 2)) * 40 + 2 * (lane & 3);

    #pragma unroll 1
    for (int s = 0; s < S; s++) {
        if (s == S - 1) asm volatile("cp.async.wait_group 0;" ::: "memory");
        else            asm volatile("cp.async.wait_group 1;" ::: "memory");
        __syncthreads();
        const float* ab = aB + (s & 1) * 5120;
        const float* bb = bB + (s & 1) * 7680;
        #pragma unroll
        for (int kg = 0; kg < 4; kg++) {
            const int off = kg * 8;
            const float2 a00 = *(const float2*)(ab + off);
            const float2 a01 = *(const float2*)(ab + 8 * 40 + off);
            const float2 a10 = *(const float2*)(ab + 16 * 40 + off);
            const float2 a11 = *(const float2*)(ab + 24 * 40 + off);
            float2 bf[12];
            #pragma unroll
            for (int j = 0; j < 12; j++)
                bf[j] = *(const float2*)(bb + ((j >> 1) * 32 + (j & 1) * 8) * 40 + off);
            #pragma unroll
            for (int j = 0; j < 12; j++) {
                mma8(acc0[j], a00, a01, bf[j]);
                mma8(acc1[j], a10, a11, bf[j]);
            }
        }
        __syncthreads();
        if (s + 2 < S) stage_load<K>(sAu, sBu, A, W, m0, c0, s + 2, tid);
    }

    // -------- epilogue: activations fused in registers --------
    #pragma unroll
    for (int im = 0; im < 2; im++) {
        float (*acc)[4] = im ? acc1 : acc0;
        #pragma unroll
        for (int rh = 0; rh < 2; rh++) {
            const int m = m0 + wm * 32 + im * 16 + rh * 8 + (lane >> 2);
            const int bb2 = m >> 8;
            const bool lastt = (m & 255) == 255;
            #pragma unroll
            for (int q = 0; q < 2; q++) {
                const int hcl = wn * 16 + q * 8 + 2 * (lane & 3);
                float hf[2], hbk[2], cfv[2], hs[2];
                #pragma unroll
                for (int j2 = 0; j2 < 2; j2++) {
                    const int c  = rh * 2 + j2;
                    const int hc = hcl + j2;
                    const float zi = acc[0 + q][c]  + sbias[hc];
                    const float zg = acc[2 + q][c]  + sbias[32 + hc];
                    const float zo = acc[4 + q][c]  + sbias[64 + hc];
                    const float cc = sigm(zi) * tanh_ap(zg);
                    const float h0 = sigm(zo) * tanh_ap(cc);
                    const float yi = acc[6 + q][c]  + sbias[96 + hc];
                    const float yg = acc[8 + q][c]  + sbias[128 + hc];
                    const float yo = acc[10 + q][c] + sbias[160 + hc];
                    const float cb = sigm(yi) * tanh_ap(yg);
                    const float h1 = sigm(yo) * tanh_ap(cb);
                    hf[j2] = h0; hbk[j2] = h1; cfv[j2] = cc; hs[j2] = h0 + h1;
                }
                const int hcg = c0 + hcl;
                *(float2*)(out + OUT_ENC_OFF + ((size_t)m * 2 + LAYER) * 512 + hcg) =
                    make_float2(hs[0], hs[1]);
                if (LAYER == 0) {
                    float* ip = g_inp1 + (size_t)m * 1024;
                    ip[kslot(hcg)]       = tf32r(hf[0]);
                    ip[kslot(hcg + 1)]   = tf32r(hf[1]);
                    ip[kslot(512 + hcg)]     = tf32r(hbk[0]);
                    ip[kslot(512 + hcg + 1)] = tf32r(hbk[1]);
                }
                if (lastt) {
                    *(float2*)(out + (LAYER * 32 + bb2) * 512 + hcg) =
                        make_float2(hf[0], hf[1]);
                    *(float2*)(out + OUT_C_OFF + (LAYER * 32 + bb2) * 512 + hcg) =
                        make_float2(cfv[0], cfv[1]);
                }
            }
        }
    }
}

// ---------------- prep kernels ----------------
__global__ void prep_emb(const int* __restrict__ x, const float* __restrict__ emb) {
    const int m = blockIdx.x;
    const float4 v = ((const float4*)(emb + (size_t)x[m] * 512))[threadIdx.x];
    const int L = threadIdx.x * 4;
    float* dst = g_a0 + (size_t)m * 512;
    dst[kslot(L)]     = tf32r(v.x);
    dst[kslot(L + 1)] = tf32r(v.y);
    dst[kslot(L + 2)] = tf32r(v.z);
    dst[kslot(L + 3)] = tf32r(v.w);
}

template <int K, int WHICH>
__global__ void prep_w(const float* __restrict__ Wsrc) {
    const int base[6] = {0, 1024, 1536, 2048, 3072, 3584};
    const int row = blockIdx.x;
    const int g = row >> 9, c = row & 511;
    const float4 v = ((const float4*)(Wsrc + (size_t)(base[g] + c) * K))[threadIdx.x];
    float* dst = (WHICH ? g_w1 : g_w0) + (size_t)row * K;
    const int L = threadIdx.x * 4;
    dst[kslot(L)]     = tf32r(v.x);
    dst[kslot(L + 1)] = tf32r(v.y);
    dst[kslot(L + 2)] = tf32r(v.z);
    dst[kslot(L + 3)] = tf32r(v.w);
}

__global__ void prep_bias(const float* __restrict__ bi0, const float* __restrict__ bh0,
                          const float* __restrict__ bi1, const float* __restrict__ bh1) {
    const int base[6] = {0, 1024, 1536, 2048, 3072, 3584};
    const int i = blockIdx.x * 256 + threadIdx.x;     // 0..6143
    const int row = (i < 3072) ? i : i - 3072;
    const int g = row >> 9, c = row & 511;
    const int r = base[g] + c;
    if (i < 3072) g_b0[row] = bi0[r] + bh0[r];
    else          g_b1[row] = bi1[r] + bh1[r];
}

// ---------------- launch ----------------
extern "C" void kernel_launch(void* const* d_in, const int* in_sizes, int n_in,
                              void* d_out, int out_size)
{
    const int*   x   = (const int*)  d_in[0];
    const float* emb = (const float*)d_in[1];
    const float* W0  = (const float*)d_in[2];
    const float* bi0 = (const float*)d_in[4];
    const float* bh0 = (const float*)d_in[5];
    const float* W1  = (const float*)d_in[6];
    const float* bi1 = (const float*)d_in[8];
    const float* bh1 = (const float*)d_in[9];
    float* out = (float*)d_out;

    const int SMEM = 25792 * 4;   // 103168 bytes
    cudaFuncSetAttribute(lstm_mma<512, 0>,  cudaFuncAttributeMaxDynamicSharedMemorySize, SMEM);
    cudaFuncSetAttribute(lstm_mma<1024, 1>, cudaFuncAttributeMaxDynamicSharedMemorySize, SMEM);

    prep_emb<<<8192, 128>>>(x, emb);
    prep_w<512, 0><<<3072, 128>>>(W0);
    prep_w<1024, 1><<<3072, 256>>>(W1);
    prep_bias<<<24, 256>>>(bi0, bh0, bi1, bh1);

    dim3 g(64, 16);
    lstm_mma<512, 0><<<g, 256, SMEM>>>(out);
    lstm_mma<1024, 1><<<g, 256, SMEM>>>(out);
}

// round 7
// speedup vs baseline: 5.3435x; 1.6587x over previous
#include <cuda_runtime.h>
#include <cuda_fp16.h>
#include <cstdint>

// ---------------- problem constants ----------------
#define OUT_C_OFF   (2 * 32 * 512)
#define OUT_ENC_OFF (4 * 32 * 512)

// ---------------- device scratch (no allocs allowed) ----------------
// All GEMM operands are rn-rounded to fp16 and k-permuted within each 16-column
// group to slot order [0,1,8,9, 2,3,10,11, 4,5,12,13, 6,7,14,15] so each
// thread's m16n8k16 fragment (k = 2q,2q+1,2q+8,2q+9) is one contiguous LDS.64.
__device__ __half g_a0[(size_t)8192 * 512];     // gathered embeddings
__device__ __half g_w0[(size_t)3072 * 512];     // L0 weights, gate-major rows: i_f,g_f,o_f,i_b,g_b,o_b
__device__ __half g_w1[(size_t)3072 * 1024];    // L1 weights, gate-major rows
__device__ __half g_inp1[(size_t)8192 * 1024];  // L0 output h (permuted): [h_f | h_b]
__device__ float g_b0[3072];                    // combined biases, gate-major
__device__ float g_b1[3072];

// ---------------- helpers ----------------
__device__ __forceinline__ float tanh_ap(float x) {
    float r; asm("tanh.approx.f32 %0, %1;" : "=f"(r) : "f"(x)); return r;
}
__device__ __forceinline__ float sigm(float x) { return 0.5f * tanh_ap(0.5f * x) + 0.5f; }

__device__ __forceinline__ uint32_t s2u(const void* p) {
    uint32_t a;
    asm("{ .reg .u64 t; cvta.to.shared.u64 t, %1; cvt.u32.u64 %0, t; }" : "=r"(a) : "l"(p));
    return a;
}
__device__ __forceinline__ void cp16(uint32_t d, const void* s) {
    asm volatile("cp.async.cg.shared.global [%0], [%1], 16;" :: "r"(d), "l"(s));
}

// inverse permutation: logical k L -> stored slot (within 16-group)
__device__ __forceinline__ int kslot16(int L) {
    const int r = L & 15, base = L & ~15;
    return base + ((r < 8) ? (((r >> 1) << 2) + (r & 1))
                           : ((((r - 8) >> 1) << 2) + 2 + (r & 1)));
}

// m16n8k16 fp16 HMMA, fp32 accum.
// lo = row r  regs {a0 (k0-7 pair), a2 (k8-15 pair)}, hi = row r+8 {a1, a3}.
__device__ __forceinline__ void mma16(float* d, uint2 lo, uint2 hi, uint2 b) {
    asm volatile(
        "mma.sync.aligned.m16n8k16.row.col.f32.f16.f16.f32 "
        "{%0,%1,%2,%3},{%4,%5,%6,%7},{%8,%9},{%0,%1,%2,%3};"
        : "+f"(d[0]), "+f"(d[1]), "+f"(d[2]), "+f"(d[3])
        : "r"(lo.x), "r"(hi.x), "r"(lo.y), "r"(hi.y), "r"(b.x), "r"(b.y));
}

// ---------------- stage loader (cp.async, double buffer) ----------------
// Stage = 64 k (128B of halves per row). Row stride 144B (72 halves).
// A: 128 rows, B: 192 rows (6 gates x 32 cols).
#define ROWB 144
#define ROWH 72
#define STAGE_A_B (128 * ROWB)     // 18432 bytes
#define STAGE_B_B (192 * ROWB)     // 27648 bytes
#define SB_OFF_B  (2 * STAGE_A_B)  // 36864
#define BIAS_OFF_B (SB_OFF_B + 2 * STAGE_B_B)   // 92160
#define SMEM_TOT  (BIAS_OFF_B + 192 * 4)        // 92928

template <int K>
__device__ __forceinline__ void stage_load(uint32_t sbu,
                                           const __half* __restrict__ A,
                                           const __half* __restrict__ W,
                                           int m0, int c0, int s, int tid) {
    const int k0 = s * 64;
    const int b  = s & 1;
    // A: 128 rows x 8 chunks(16B); 2 threads/row, 4 chunks each
    const int ar = tid >> 1, ac0 = (tid & 1) * 4;
    const __half* asrc = A + (size_t)(m0 + ar) * K + k0;
    const uint32_t ad = sbu + b * STAGE_A_B + ar * ROWB;
    #pragma unroll
    for (int i = 0; i < 4; i++) cp16(ad + (ac0 + i) * 16, asrc + (ac0 + i) * 8);
    // B: 192 rows x 8 chunks; 6 chunks per thread
    const uint32_t wd = sbu + SB_OFF_B + b * STAGE_B_B;
    #pragma unroll
    for (int i = 0; i < 6; i++) {
        const int u = tid + 256 * i;
        const int r = u >> 3, ch = u & 7;
        const __half* wsrc = W + (size_t)((r >> 5) * 512 + c0 + (r & 31)) * K + k0 + ch * 8;
        cp16(wd + r * ROWB + ch * 16, wsrc);
    }
    asm volatile("cp.async.commit_group;" ::: "memory");
}

// ---------------- fused LSTM layer (mma.sync fp16, fp32 accum) ----------------
// CTA: 128 m-rows x 32 h-cols, 6 gate blocks (N_eff = 192). 8 warps = 4(m) x 2(n).
template <int K, int LAYER>
__global__ void __launch_bounds__(256, 1)
lstm_mma(float* __restrict__ out)
{
    constexpr int S = K / 64;       // 8 (L0) or 16 (L1)
    extern __shared__ char smraw[];
    __half* sA = (__half*)smraw;
    __half* sB = (__half*)(smraw + SB_OFF_B);
    float* sbias = (float*)(smraw + BIAS_OFF_B);

    const __half* A  = LAYER ? g_inp1 : g_a0;
    const __half* W  = LAYER ? g_w1   : g_w0;
    const float*  bv = LAYER ? g_b1   : g_b0;

    const int tid = threadIdx.x, lane = tid & 31, w = tid >> 5;
    const int wm = w & 3, wn = w >> 2;
    const int m0 = blockIdx.x * 128, c0 = blockIdx.y * 32;

    if (tid < 192) sbias[tid] = bv[(tid >> 5) * 512 + c0 + (tid & 31)];

    const uint32_t sbu = s2u(smraw);

    float acc0[12][4] = {}, acc1[12][4] = {};   // [gate*2+q][c] for m-tiles 0/1

    stage_load<K>(sbu, A, W, m0, c0, 0, tid);
    stage_load<K>(sbu, A, W, m0, c0, 1, tid);

    const __half* aB = sA + (wm * 32 + (lane >> 2)) * ROWH + 4 * (lane & 3);
    const __half* bB = sB + (wn * 16 + (lane >> 2)) * ROWH + 4 * (lane & 3);

    #pragma unroll 1
    for (int s = 0; s < S; s++) {
        if (s == S - 1) asm volatile("cp.async.wait_group 0;" ::: "memory");
        else            asm volatile("cp.async.wait_group 1;" ::: "memory");
        __syncthreads();
        const __half* ab = aB + (s & 1) * (STAGE_A_B / 2);
        const __half* bb = bB + (s & 1) * (STAGE_B_B / 2);
        #pragma unroll
        for (int kg = 0; kg < 4; kg++) {
            const __half* abk = ab + kg * 16;
            const __half* bbk = bb + kg * 16;
            const uint2 A00 = *(const uint2*)(abk);                    // im0 row r
            const uint2 A01 = *(const uint2*)(abk + 8 * ROWH);         // im0 row r+8
            const uint2 A10 = *(const uint2*)(abk + 16 * ROWH);        // im1 row r
            const uint2 A11 = *(const uint2*)(abk + 24 * ROWH);        // im1 row r+8
            uint2 bf[12];
            #pragma unroll
            for (int j = 0; j < 12; j++)
                bf[j] = *(const uint2*)(bbk + ((j >> 1) * 32 + (j & 1) * 8) * ROWH);
            #pragma unroll
            for (int j = 0; j < 12; j++) {
                mma16(acc0[j], A00, A01, bf[j]);
                mma16(acc1[j], A10, A11, bf[j]);
            }
        }
        __syncthreads();
        if (s + 2 < S) stage_load<K>(sbu, A, W, m0, c0, s + 2, tid);
    }

    // -------- epilogue: activations fused in registers --------
    #pragma unroll
    for (int im = 0; im < 2; im++) {
        float (*acc)[4] = im ? acc1 : acc0;
        #pragma unroll
        for (int rh = 0; rh < 2; rh++) {
            const int m = m0 + wm * 32 + im * 16 + rh * 8 + (lane >> 2);
            const int bb2 = m >> 8;
            const bool lastt = (m & 255) == 255;
            #pragma unroll
            for (int q = 0; q < 2; q++) {
                const int hcl = wn * 16 + q * 8 + 2 * (lane & 3);
                float hf[2], hbk[2], cfv[2], hs[2];
                #pragma unroll
                for (int j2 = 0; j2 < 2; j2++) {
                    const int c  = rh * 2 + j2;
                    const int hc = hcl + j2;
                    const float zi = acc[0 + q][c]  + sbias[hc];
                    const float zg = acc[2 + q][c]  + sbias[32 + hc];
                    const float zo = acc[4 + q][c]  + sbias[64 + hc];
                    const float cc = sigm(zi) * tanh_ap(zg);
                    const float h0 = sigm(zo) * tanh_ap(cc);
                    const float yi = acc[6 + q][c]  + sbias[96 + hc];
                    const float yg = acc[8 + q][c]  + sbias[128 + hc];
                    const float yo = acc[10 + q][c] + sbias[160 + hc];
                    const float cb = sigm(yi) * tanh_ap(yg);
                    const float h1 = sigm(yo) * tanh_ap(cb);
                    hf[j2] = h0; hbk[j2] = h1; cfv[j2] = cc; hs[j2] = h0 + h1;
                }
                const int hcg = c0 + hcl;
                *(float2*)(out + OUT_ENC_OFF + ((size_t)m * 2 + LAYER) * 512 + hcg) =
                    make_float2(hs[0], hs[1]);
                if (LAYER == 0) {
                    __half* ip = g_inp1 + (size_t)m * 1024;
                    *(__half2*)(ip + kslot16(hcg))       = __floats2half2_rn(hf[0], hf[1]);
                    *(__half2*)(ip + kslot16(512 + hcg)) = __floats2half2_rn(hbk[0], hbk[1]);
                }
                if (lastt) {
                    *(float2*)(out + (LAYER * 32 + bb2) * 512 + hcg) =
                        make_float2(hf[0], hf[1]);
                    *(float2*)(out + OUT_C_OFF + (LAYER * 32 + bb2) * 512 + hcg) =
                        make_float2(cfv[0], cfv[1]);
                }
            }
        }
    }
}

// ---------------- prep kernels ----------------
__constant__ int c_perm[16] = {0,1,8,9, 2,3,10,11, 4,5,12,13, 6,7,14,15};

__global__ void prep_emb(const int* __restrict__ x, const float* __restrict__ emb) {
    const int id = blockIdx.x * 256 + threadIdx.x;   // 8192 rows * 32 groups
    const int m = id >> 5, grp = id & 31;
    const float* src = emb + (size_t)x[m] * 512 + grp * 16;
    __half2 h[8];
    #pragma unroll
    for (int j = 0; j < 8; j++)
        h[j] = __floats2half2_rn(src[c_perm[2 * j]], src[c_perm[2 * j + 1]]);
    uint4* dst = (uint4*)(g_a0 + (size_t)m * 512 + grp * 16);
    dst[0] = *(uint4*)&h[0];
    dst[1] = *(uint4*)&h[4];
}

template <int K, int WHICH>
__global__ void prep_w(const float* __restrict__ Wsrc) {
    const int base[6] = {0, 1024, 1536, 2048, 3072, 3584};
    const int id = blockIdx.x * 256 + threadIdx.x;   // 3072 rows * (K/16) groups
    const int row = id / (K / 16), grp = id % (K / 16);
    const int g = row >> 9, c = row & 511;
    const float* src = Wsrc + (size_t)(base[g] + c) * K + grp * 16;
    __half2 h[8];
    #pragma unroll
    for (int j = 0; j < 8; j++)
        h[j] = __floats2half2_rn(src[c_perm[2 * j]], src[c_perm[2 * j + 1]]);
    uint4* dst = (uint4*)((WHICH ? g_w1 : g_w0) + (size_t)row * K + grp * 16);
    dst[0] = *(uint4*)&h[0];
    dst[1] = *(uint4*)&h[4];
}

__global__ void prep_bias(const float* __restrict__ bi0, const float* __restrict__ bh0,
                          const float* __restrict__ bi1, const float* __restrict__ bh1) {
    const int base[6] = {0, 1024, 1536, 2048, 3072, 3584};
    const int i = blockIdx.x * 256 + threadIdx.x;     // 0..6143
    const int row = (i < 3072) ? i : i - 3072;
    const int g = row >> 9, c = row & 511;
    const int r = base[g] + c;
    if (i < 3072) g_b0[row] = bi0[r] + bh0[r];
    else          g_b1[row] = bi1[r] + bh1[r];
}

// ---------------- launch ----------------
extern "C" void kernel_launch(void* const* d_in, const int* in_sizes, int n_in,
                              void* d_out, int out_size)
{
    const int*   x   = (const int*)  d_in[0];
    const float* emb = (const float*)d_in[1];
    const float* W0  = (const float*)d_in[2];
    const float* bi0 = (const float*)d_in[4];
    const float* bh0 = (const float*)d_in[5];
    const float* W1  = (const float*)d_in[6];
    const float* bi1 = (const float*)d_in[8];
    const float* bh1 = (const float*)d_in[9];
    float* out = (float*)d_out;

    cudaFuncSetAttribute(lstm_mma<512, 0>,  cudaFuncAttributeMaxDynamicSharedMemorySize, SMEM_TOT);
    cudaFuncSetAttribute(lstm_mma<1024, 1>, cudaFuncAttributeMaxDynamicSharedMemorySize, SMEM_TOT);

    prep_emb<<<1024, 256>>>(x, emb);                 // 8192*32 groups
    prep_w<512, 0><<<384, 256>>>(W0);                // 3072*32 groups
    prep_w<1024, 1><<<768, 256>>>(W1);               // 3072*64 groups
    prep_bias<<<24, 256>>>(bi0, bh0, bi1, bh1);

    dim3 g(64, 16);
    lstm_mma<512, 0><<<g, 256, SMEM_TOT>>>(out);
    lstm_mma<1024, 1><<<g, 256, SMEM_TOT>>>(out);
}

// round 8
// speedup vs baseline: 5.5180x; 1.0326x over previous
#include <cuda_runtime.h>
#include <cuda_fp16.h>
#include <cstdint>

// ---------------- problem constants ----------------
#define OUT_C_OFF   (2 * 32 * 512)
#define OUT_ENC_OFF (4 * 32 * 512)

// ---------------- device scratch (no allocs allowed) ----------------
// GEMM operands rn-rounded to fp16, k-permuted within each 16-group to
// [0,1,8,9, 2,3,10,11, 4,5,12,13, 6,7,14,15] so each thread's m16n8k16
// fragment (k = 2q,2q+1,2q+8,2q+9) is one contiguous LDS.64.
__device__ __half g_a0[(size_t)8192 * 512];     // gathered embeddings
__device__ __half g_w0[(size_t)3072 * 512];     // L0 weights, gate-major: i_f,g_f,o_f,i_b,g_b,o_b
__device__ __half g_w1[(size_t)3072 * 1024];    // L1 weights, gate-major
__device__ __half g_inp1[(size_t)8192 * 1024];  // L0 output h (permuted): [h_f | h_b]

// ---------------- helpers ----------------
__device__ __forceinline__ float tanh_ap(float x) {
    float r; asm("tanh.approx.f32 %0, %1;" : "=f"(r) : "f"(x)); return r;
}
__device__ __forceinline__ float sigm(float x) { return 0.5f * tanh_ap(0.5f * x) + 0.5f; }

__device__ __forceinline__ uint32_t s2u(const void* p) {
    uint32_t a;
    asm("{ .reg .u64 t; cvta.to.shared.u64 t, %1; cvt.u32.u64 %0, t; }" : "=r"(a) : "l"(p));
    return a;
}
__device__ __forceinline__ void cp16(uint32_t d, const void* s) {
    asm volatile("cp.async.cg.shared.global [%0], [%1], 16;" :: "r"(d), "l"(s));
}

// logical k L -> stored slot (within 16-group)
__device__ __forceinline__ int kslot16(int L) {
    const int r = L & 15, base = L & ~15;
    return base + ((r < 8) ? (((r >> 1) << 2) + (r & 1))
                           : ((((r - 8) >> 1) << 2) + 2 + (r & 1)));
}

// gate g (0..5 = i_f,g_f,o_f,i_b,g_b,o_b) -> row base in (2,4H) space
__device__ __forceinline__ int gbase(int g) {
    const int d = (g >= 3) ? 1 : 0;
    const int g3 = g - 3 * d;
    return d * 2048 + ((g3 == 1) ? 1024 : (g3 == 2) ? 1536 : 0);
}

// m16n8k16 fp16 HMMA, fp32 accum
__device__ __forceinline__ void mma16(float* d, uint2 lo, uint2 hi, uint2 b) {
    asm volatile(
        "mma.sync.aligned.m16n8k16.row.col.f32.f16.f16.f32 "
        "{%0,%1,%2,%3},{%4,%5,%6,%7},{%8,%9},{%0,%1,%2,%3};"
        : "+f"(d[0]), "+f"(d[1]), "+f"(d[2]), "+f"(d[3])
        : "r"(lo.x), "r"(hi.x), "r"(lo.y), "r"(hi.y), "r"(b.x), "r"(b.y));
}

// ---------------- smem layout: 3-stage multibuffer ----------------
// Stage = 64 k (128B of halves per row), row stride 144B. A:128 rows, B:192 rows.
#define ROWB 144
#define ROWH 72
#define STAGE_A_B (128 * ROWB)              // 18432
#define STAGE_B_B (192 * ROWB)              // 27648
#define SB_OFF_B  (3 * STAGE_A_B)           // 55296
#define BIAS_OFF_B (SB_OFF_B + 3 * STAGE_B_B)   // 138240
#define SMEM_TOT  (BIAS_OFF_B + 192 * 4)        // 139008

template <int K>
__device__ __forceinline__ void stage_load(uint32_t sbu,
                                           const __half* __restrict__ A,
                                           const __half* __restrict__ W,
                                           int m0, int c0, int s, int tid) {
    const int k0 = s * 64;
    const int b  = s % 3;
    // A: 128 rows x 8 chunks(16B); 2 threads/row, 4 chunks each
    const int ar = tid >> 1, ac0 = (tid & 1) * 4;
    const __half* asrc = A + (size_t)(m0 + ar) * K + k0;
    const uint32_t ad = sbu + b * STAGE_A_B + ar * ROWB;
    #pragma unroll
    for (int i = 0; i < 4; i++) cp16(ad + (ac0 + i) * 16, asrc + (ac0 + i) * 8);
    // B: 192 rows x 8 chunks; 6 chunks per thread
    const uint32_t wd = sbu + SB_OFF_B + b * STAGE_B_B;
    #pragma unroll
    for (int i = 0; i < 6; i++) {
        const int u = tid + 256 * i;
        const int r = u >> 3, ch = u & 7;
        const __half* wsrc = W + (size_t)((r >> 5) * 512 + c0 + (r & 31)) * K + k0 + ch * 8;
        cp16(wd + r * ROWB + ch * 16, wsrc);
    }
    asm volatile("cp.async.commit_group;" ::: "memory");
}

// ---------------- fused LSTM layer (mma.sync fp16, fp32 accum) ----------------
// CTA: 128 m-rows x 32 h-cols, 6 gate blocks (N_eff = 192). 8 warps = 4(m) x 2(n).
template <int K, int LAYER>
__global__ void __launch_bounds__(256, 1)
lstm_mma(const float* __restrict__ bi, const float* __restrict__ bh,
         float* __restrict__ out)
{
    constexpr int S = K / 64;       // 8 (L0) or 16 (L1)
    extern __shared__ char smraw[];
    __half* sA = (__half*)smraw;
    __half* sB = (__half*)(smraw + SB_OFF_B);
    float* sbias = (float*)(smraw + BIAS_OFF_B);

    const __half* A = LAYER ? g_inp1 : g_a0;
    const __half* W = LAYER ? g_w1   : g_w0;

    const int tid = threadIdx.x, lane = tid & 31, w = tid >> 5;
    const int wm = w & 3, wn = w >> 2;
    const int m0 = blockIdx.x * 128, c0 = blockIdx.y * 32;

    const uint32_t sbu = s2u(smraw);

    stage_load<K>(sbu, A, W, m0, c0, 0, tid);

    if (tid < 192) {
        const int gr = gbase(tid >> 5) + c0 + (tid & 31);
        sbias[tid] = bi[gr] + bh[gr];
    }

    stage_load<K>(sbu, A, W, m0, c0, 1, tid);

    float acc0[12][4] = {}, acc1[12][4] = {};   // [gate*2+q][c] for m-tiles 0/1

    const __half* aB = sA + (wm * 32 + (lane >> 2)) * ROWH + 4 * (lane & 3);
    const __half* bB = sB + (wn * 16 + (lane >> 2)) * ROWH + 4 * (lane & 3);

    #pragma unroll 1
    for (int s = 0; s < S; s++) {
        asm volatile("cp.async.wait_group 1;" ::: "memory");
        __syncthreads();
        if (s + 2 < S) stage_load<K>(sbu, A, W, m0, c0, s + 2, tid);

        const int buf = s % 3;
        const __half* ab = aB + buf * (STAGE_A_B / 2);
        const __half* bb = bB + buf * (STAGE_B_B / 2);
        #pragma unroll
        for (int kg = 0; kg < 4; kg++) {
            const __half* abk = ab + kg * 16;
            const __half* bbk = bb + kg * 16;
            const uint2 A00 = *(const uint2*)(abk);
            const uint2 A01 = *(const uint2*)(abk + 8 * ROWH);
            const uint2 A10 = *(const uint2*)(abk + 16 * ROWH);
            const uint2 A11 = *(const uint2*)(abk + 24 * ROWH);
            uint2 bf[12];
            #pragma unroll
            for (int j = 0; j < 12; j++)
                bf[j] = *(const uint2*)(bbk + ((j >> 1) * 32 + (j & 1) * 8) * ROWH);
            #pragma unroll
            for (int j = 0; j < 12; j++) {
                mma16(acc0[j], A00, A01, bf[j]);
                mma16(acc1[j], A10, A11, bf[j]);
            }
        }
    }

    // -------- epilogue: activations fused in registers --------
    #pragma unroll
    for (int im = 0; im < 2; im++) {
        float (*acc)[4] = im ? acc1 : acc0;
        #pragma unroll
        for (int rh = 0; rh < 2; rh++) {
            const int m = m0 + wm * 32 + im * 16 + rh * 8 + (lane >> 2);
            const int bb2 = m >> 8;
            const bool lastt = (m & 255) == 255;
            #pragma unroll
            for (int q = 0; q < 2; q++) {
                const int hcl = wn * 16 + q * 8 + 2 * (lane & 3);
                float hf[2], hbk[2], cfv[2], hs[2];
                #pragma unroll
                for (int j2 = 0; j2 < 2; j2++) {
                    const int c  = rh * 2 + j2;
                    const int hc = hcl + j2;
                    const float zi = acc[0 + q][c]  + sbias[hc];
                    const float zg = acc[2 + q][c]  + sbias[32 + hc];
                    const float zo = acc[4 + q][c]  + sbias[64 + hc];
                    const float cc = sigm(zi) * tanh_ap(zg);
                    const float h0 = sigm(zo) * tanh_ap(cc);
                    const float yi = acc[6 + q][c]  + sbias[96 + hc];
                    const float yg = acc[8 + q][c]  + sbias[128 + hc];
                    const float yo = acc[10 + q][c] + sbias[160 + hc];
                    const float cb = sigm(yi) * tanh_ap(yg);
                    const float h1 = sigm(yo) * tanh_ap(cb);
                    hf[j2] = h0; hbk[j2] = h1; cfv[j2] = cc; hs[j2] = h0 + h1;
                }
                const int hcg = c0 + hcl;
                *(float2*)(out + OUT_ENC_OFF + ((size_t)m * 2 + LAYER) * 512 + hcg) =
                    make_float2(hs[0], hs[1]);
                if (LAYER == 0) {
                    __half* ip = g_inp1 + (size_t)m * 1024;
                    *(__half2*)(ip + kslot16(hcg))       = __floats2half2_rn(hf[0], hf[1]);
                    *(__half2*)(ip + kslot16(512 + hcg)) = __floats2half2_rn(hbk[0], hbk[1]);
                }
                if (lastt) {
                    *(float2*)(out + (LAYER * 32 + bb2) * 512 + hcg) =
                        make_float2(hf[0], hf[1]);
                    *(float2*)(out + OUT_C_OFF + (LAYER * 32 + bb2) * 512 + hcg) =
                        make_float2(cfv[0], cfv[1]);
                }
            }
        }
    }
}

// ---------------- single merged prep kernel ----------------
__constant__ int c_perm[16] = {0,1,8,9, 2,3,10,11, 4,5,12,13, 6,7,14,15};

__device__ __forceinline__ void conv16(const float* __restrict__ src, __half* __restrict__ dst) {
    __half2 h[8];
    #pragma unroll
    for (int j = 0; j < 8; j++)
        h[j] = __floats2half2_rn(src[c_perm[2 * j]], src[c_perm[2 * j + 1]]);
    ((uint4*)dst)[0] = *(uint4*)&h[0];
    ((uint4*)dst)[1] = *(uint4*)&h[4];
}

// ranges: [0,262144) emb | [262144,360448) w0 | [360448,557056) w1
__global__ void prep_all(const int* __restrict__ x, const float* __restrict__ emb,
                         const float* __restrict__ W0, const float* __restrict__ W1) {
    const int id = blockIdx.x * 256 + threadIdx.x;
    if (id < 262144) {
        const int m = id >> 5, grp = id & 31;
        conv16(emb + (size_t)x[m] * 512 + grp * 16, g_a0 + (size_t)m * 512 + grp * 16);
    } else if (id < 360448) {
        const int u = id - 262144;
        const int row = u >> 5, grp = u & 31;
        conv16(W0 + (size_t)(gbase(row >> 9) + (row & 511)) * 512 + grp * 16,
               g_w0 + (size_t)row * 512 + grp * 16);
    } else {
        const int u = id - 360448;
        const int row = u >> 6, grp = u & 63;
        conv16(W1 + (size_t)(gbase(row >> 9) + (row & 511)) * 1024 + grp * 16,
               g_w1 + (size_t)row * 1024 + grp * 16);
    }
}

// ---------------- launch ----------------
extern "C" void kernel_launch(void* const* d_in, const int* in_sizes, int n_in,
                              void* d_out, int out_size)
{
    const int*   x   = (const int*)  d_in[0];
    const float* emb = (const float*)d_in[1];
    const float* W0  = (const float*)d_in[2];
    const float* bi0 = (const float*)d_in[4];
    const float* bh0 = (const float*)d_in[5];
    const float* W1  = (const float*)d_in[6];
    const float* bi1 = (const float*)d_in[8];
    const float* bh1 = (const float*)d_in[9];
    float* out = (float*)d_out;

    cudaFuncSetAttribute(lstm_mma<512, 0>,  cudaFuncAttributeMaxDynamicSharedMemorySize, SMEM_TOT);
    cudaFuncSetAttribute(lstm_mma<1024, 1>, cudaFuncAttributeMaxDynamicSharedMemorySize, SMEM_TOT);

    prep_all<<<2176, 256>>>(x, emb, W0, W1);

    dim3 g(64, 16);
    lstm_mma<512, 0><<<g, 256, SMEM_TOT>>>(bi0, bh0, out);
    lstm_mma<1024, 1><<<g, 256, SMEM_TOT>>>(bi1, bh1, out);
}

// round 10
// speedup vs baseline: 5.6785x; 1.0291x over previous
#include <cuda_runtime.h>
#include <cuda_fp16.h>
#include <cstdint>

// ---------------- problem constants ----------------
#define OUT_C_OFF   (2 * 32 * 512)
#define OUT_ENC_OFF (4 * 32 * 512)

// ---------------- device scratch (no allocs allowed) ----------------
// GEMM operands rn-rounded to fp16, k-permuted within each 16-group to
// [0,1,8,9, 2,3,10,11, 4,5,12,13, 6,7,14,15] so each thread's m16n8k16
// fragment (k = 2q,2q+1,2q+8,2q+9) is one contiguous LDS.64.
__device__ __half g_a0[(size_t)8192 * 512];     // gathered embeddings
__device__ __half g_w0[(size_t)3072 * 512];     // L0 weights, gate-major: i_f,g_f,o_f,i_b,g_b,o_b
__device__ __half g_w1[(size_t)3072 * 1024];    // L1 weights, gate-major
__device__ __half g_inp1[(size_t)8192 * 1024];  // L0 output h (permuted): [h_f | h_b]

// ---------------- helpers ----------------
__device__ __forceinline__ float tanh_ap(float x) {
    float r; asm("tanh.approx.f32 %0, %1;" : "=f"(r) : "f"(x)); return r;
}
__device__ __forceinline__ float sigm(float x) { return 0.5f * tanh_ap(0.5f * x) + 0.5f; }

__device__ __forceinline__ uint32_t s2u(const void* p) {
    uint32_t a;
    asm("{ .reg .u64 t; cvta.to.shared.u64 t, %1; cvt.u32.u64 %0, t; }" : "=r"(a) : "l"(p));
    return a;
}
__device__ __forceinline__ void cp16(uint32_t d, const void* s) {
    asm volatile("cp.async.cg.shared.global [%0], [%1], 16;" :: "r"(d), "l"(s));
}

// logical k L -> stored slot (within 16-group)
__device__ __forceinline__ int kslot16(int L) {
    const int r = L & 15, base = L & ~15;
    return base + ((r < 8) ? (((r >> 1) << 2) + (r & 1))
                           : ((((r - 8) >> 1) << 2) + 2 + (r & 1)));
}

// gate g (0..5 = i_f,g_f,o_f,i_b,g_b,o_b) -> row base in (2,4H) space
__device__ __forceinline__ int gbase(int g) {
    const int d = (g >= 3) ? 1 : 0;
    const int g3 = g - 3 * d;
    return d * 2048 + ((g3 == 1) ? 1024 : (g3 == 2) ? 1536 : 0);
}

// vectorized fp16 convert + 16-group permute: 4 contiguous LDG.128 in, 2 STG.128 out
__device__ __forceinline__ void conv16v(const float* __restrict__ src, __half* __restrict__ dst) {
    const float4 v0 = ((const float4*)src)[0];   // k0..3
    const float4 v1 = ((const float4*)src)[1];   // k4..7
    const float4 v2 = ((const float4*)src)[2];   // k8..11
    const float4 v3 = ((const float4*)src)[3];   // k12..15
    __half2 h[8];
    h[0] = __floats2half2_rn(v0.x, v0.y);   // k0,k1
    h[1] = __floats2half2_rn(v2.x, v2.y);   // k8,k9
    h[2] = __floats2half2_rn(v0.z, v0.w);   // k2,k3
    h[3] = __floats2half2_rn(v2.z, v2.w);   // k10,k11
    h[4] = __floats2half2_rn(v1.x, v1.y);   // k4,k5
    h[5] = __floats2half2_rn(v3.x, v3.y);   // k12,k13
    h[6] = __floats2half2_rn(v1.z, v1.w);   // k6,k7
    h[7] = __floats2half2_rn(v3.z, v3.w);   // k14,k15
    ((uint4*)dst)[0] = *(uint4*)&h[0];
    ((uint4*)dst)[1] = *(uint4*)&h[4];
}

// m16n8k16 fp16 HMMA, fp32 accum
__device__ __forceinline__ void mma16(float* d, uint2 lo, uint2 hi, uint2 b) {
    asm volatile(
        "mma.sync.aligned.m16n8k16.row.col.f32.f16.f16.f32 "
        "{%0,%1,%2,%3},{%4,%5,%6,%7},{%8,%9},{%0,%1,%2,%3};"
        : "+f"(d[0]), "+f"(d[1]), "+f"(d[2]), "+f"(d[3])
        : "r"(lo.x), "r"(hi.x), "r"(lo.y), "r"(hi.y), "r"(b.x), "r"(b.y));
}

// ---------------- smem layout: 3-stage multibuffer ----------------
// Stage = 64 k (128B of halves per row), row stride 144B. A:128 rows, B:192 rows.
#define ROWB 144
#define ROWH 72
#define STAGE_A_B (128 * ROWB)              // 18432
#define STAGE_B_B (192 * ROWB)              // 27648
#define SB_OFF_B  (3 * STAGE_A_B)           // 55296
#define BIAS_OFF_B (SB_OFF_B + 3 * STAGE_B_B)   // 138240
#define SMEM_TOT  (BIAS_OFF_B + 192 * 4)        // 139008

template <int K>
__device__ __forceinline__ void stage_load(uint32_t sbu,
                                           const __half* __restrict__ A,
                                           const __half* __restrict__ W,
                                           int m0, int c0, int s, int tid) {
    const int k0 = s * 64;
    const int b  = s % 3;
    // A: 128 rows x 8 chunks(16B); 2 threads/row, 4 chunks each
    const int ar = tid >> 1, ac0 = (tid & 1) * 4;
    const __half* asrc = A + (size_t)(m0 + ar) * K + k0;
    const uint32_t ad = sbu + b * STAGE_A_B + ar * ROWB;
    #pragma unroll
    for (int i = 0; i < 4; i++) cp16(ad + (ac0 + i) * 16, asrc + (ac0 + i) * 8);
    // B: 192 rows x 8 chunks; 6 chunks per thread
    const uint32_t wd = sbu + SB_OFF_B + b * STAGE_B_B;
    #pragma unroll
    for (int i = 0; i < 6; i++) {
        const int u = tid + 256 * i;
        const int r = u >> 3, ch = u & 7;
        const __half* wsrc = W + (size_t)((r >> 5) * 512 + c0 + (r & 31)) * K + k0 + ch * 8;
        cp16(wd + r * ROWB + ch * 16, wsrc);
    }
    asm volatile("cp.async.commit_group;" ::: "memory");
}

// ---------------- fused LSTM layer (mma.sync fp16, fp32 accum) ----------------
// CTA: 128 m-rows x 32 h-cols, 6 gate blocks (N_eff = 192). 8 warps = 4(m) x 2(n).
// PREPW1: blocks with blockIdx.y == 16 instead convert W1 -> g_w1 (hidden under
// the tensor-bound GEMM waves; kernel boundary syncs before layer 1 uses it).
template <int K, int LAYER, bool PREPW1>
__global__ void __launch_bounds__(256, 1)
lstm_mma(const float* __restrict__ bi, const float* __restrict__ bh,
         const float* __restrict__ W1src, float* __restrict__ out)
{
    constexpr int S = K / 64;       // 8 (L0) or 16 (L1)

    if (PREPW1 && blockIdx.y == 16) {
        // W1: 3072 rows x 64 groups = 196608 conv16 units; 16384 threads -> 12 each
        int gid = blockIdx.x * 256 + threadIdx.x;
        #pragma unroll 1
        for (int it = 0; it < 12; it++, gid += 16384) {
            const int row = gid >> 6, grp = gid & 63;
            conv16v(W1src + (size_t)(gbase(row >> 9) + (row & 511)) * 1024 + grp * 16,
                    g_w1 + (size_t)row * 1024 + grp * 16);
        }
        return;
    }

    extern __shared__ char smraw[];
    __half* sA = (__half*)smraw;
    __half* sB = (__half*)(smraw + SB_OFF_B);
    float* sbias = (float*)(smraw + BIAS_OFF_B);

    const __half* A = LAYER ? g_inp1 : g_a0;
    const __half* W = LAYER ? g_w1   : g_w0;

    const int tid = threadIdx.x, lane = tid & 31, w = tid >> 5;
    const int wm = w & 3, wn = w >> 2;
    const int m0 = blockIdx.x * 128, c0 = blockIdx.y * 32;

    const uint32_t sbu = s2u(smraw);

    stage_load<K>(sbu, A, W, m0, c0, 0, tid);

    if (tid < 192) {
        const int gr = gbase(tid >> 5) + c0 + (tid & 31);
        sbias[tid] = bi[gr] + bh[gr];
    }

    stage_load<K>(sbu, A, W, m0, c0, 1, tid);

    float acc0[12][4] = {}, acc1[12][4] = {};   // [gate*2+q][c] for m-tiles 0/1

    const __half* aB = sA + (wm * 32 + (lane >> 2)) * ROWH + 4 * (lane & 3);
    const __half* bB = sB + (wn * 16 + (lane >> 2)) * ROWH + 4 * (lane & 3);

    #pragma unroll 1
    for (int s = 0; s < S; s++) {
        asm volatile("cp.async.wait_group 1;" ::: "memory");
        __syncthreads();
        if (s + 2 < S) stage_load<K>(sbu, A, W, m0, c0, s + 2, tid);

        const int buf = s % 3;
        const __half* ab = aB + buf * (STAGE_A_B / 2);
        const __half* bb = bB + buf * (STAGE_B_B / 2);
        #pragma unroll
        for (int kg = 0; kg < 4; kg++) {
            const __half* abk = ab + kg * 16;
            const __half* bbk = bb + kg * 16;
            const uint2 A00 = *(const uint2*)(abk);
            const uint2 A01 = *(const uint2*)(abk + 8 * ROWH);
            const uint2 A10 = *(const uint2*)(abk + 16 * ROWH);
            const uint2 A11 = *(const uint2*)(abk + 24 * ROWH);
            uint2 bf[12];
            #pragma unroll
            for (int j = 0; j < 12; j++)
                bf[j] = *(const uint2*)(bbk + ((j >> 1) * 32 + (j & 1) * 8) * ROWH);
            #pragma unroll
            for (int j = 0; j < 12; j++) {
                mma16(acc0[j], A00, A01, bf[j]);
                mma16(acc1[j], A10, A11, bf[j]);
            }
        }
    }

    // -------- epilogue: activations fused in registers --------
    #pragma unroll
    for (int im = 0; im < 2; im++) {
        float (*acc)[4] = im ? acc1 : acc0;
        #pragma unroll
        for (int rh = 0; rh < 2; rh++) {
            const int m = m0 + wm * 32 + im * 16 + rh * 8 + (lane >> 2);
            const int bb2 = m >> 8;
            const bool lastt = (m & 255) == 255;
            #pragma unroll
            for (int q = 0; q < 2; q++) {
                const int hcl = wn * 16 + q * 8 + 2 * (lane & 3);
                float hf[2], hbk[2], cfv[2], hs[2];
                #pragma unroll
                for (int j2 = 0; j2 < 2; j2++) {
                    const int c  = rh * 2 + j2;
                    const int hc = hcl + j2;
                    const float zi = acc[0 + q][c]  + sbias[hc];
                    const float zg = acc[2 + q][c]  + sbias[32 + hc];
                    const float zo = acc[4 + q][c]  + sbias[64 + hc];
                    const float cc = sigm(zi) * tanh_ap(zg);
                    const float h0 = sigm(zo) * tanh_ap(cc);
                    const float yi = acc[6 + q][c]  + sbias[96 + hc];
                    const float yg = acc[8 + q][c]  + sbias[128 + hc];
                    const float yo = acc[10 + q][c] + sbias[160 + hc];
                    const float cb = sigm(yi) * tanh_ap(yg);
                    const float h1 = sigm(yo) * tanh_ap(cb);
                    hf[j2] = h0; hbk[j2] = h1; cfv[j2] = cc; hs[j2] = h0 + h1;
                }
                const int hcg = c0 + hcl;
                *(float2*)(out + OUT_ENC_OFF + ((size_t)m * 2 + LAYER) * 512 + hcg) =
                    make_float2(hs[0], hs[1]);
                if (LAYER == 0) {
                    __half* ip = g_inp1 + (size_t)m * 1024;
                    *(__half2*)(ip + kslot16(hcg))       = __floats2half2_rn(hf[0], hf[1]);
                    *(__half2*)(ip + kslot16(512 + hcg)) = __floats2half2_rn(hbk[0], hbk[1]);
                }
                if (lastt) {
                    *(float2*)(out + (LAYER * 32 + bb2) * 512 + hcg) =
                        make_float2(hf[0], hf[1]);
                    *(float2*)(out + OUT_C_OFF + (LAYER * 32 + bb2) * 512 + hcg) =
                        make_float2(cfv[0], cfv[1]);
                }
            }
        }
    }
}

// ---------------- prep kernel: embeddings + W0 only ----------------
// ranges: [0,262144) emb (8192 rows x 32 grp) | [262144,360448) w0 (3072 x 32)
__global__ void prep_aw0(const int* __restrict__ x, const float* __restrict__ emb,
                         const float* __restrict__ W0) {
    const int id = blockIdx.x * 256 + threadIdx.x;
    if (id < 262144) {
        const int m = id >> 5, grp = id & 31;
        conv16v(emb + (size_t)x[m] * 512 + grp * 16, g_a0 + (size_t)m * 512 + grp * 16);
    } else {
        const int u = id - 262144;
        const int row = u >> 5, grp = u & 31;
        conv16v(W0 + (size_t)(gbase(row >> 9) + (row & 511)) * 512 + grp * 16,
                g_w0 + (size_t)row * 512 + grp * 16);
    }
}

// ---------------- launch ----------------
extern "C" void kernel_launch(void* const* d_in, const int* in_sizes, int n_in,
                              void* d_out, int out_size)
{
    const int*   x   = (const int*)  d_in[0];
    const float* emb = (const float*)d_in[1];
    const float* W0  = (const float*)d_in[2];
    const float* bi0 = (const float*)d_in[4];
    const float* bh0 = (const float*)d_in[5];
    const float* W1  = (const float*)d_in[6];
    const float* bi1 = (const float*)d_in[8];
    const float* bh1 = (const float*)d_in[9];
    float* out = (float*)d_out;

    cudaFuncSetAttribute(lstm_mma<512, 0, true>,
                         cudaFuncAttributeMaxDynamicSharedMemorySize, SMEM_TOT);
    cudaFuncSetAttribute(lstm_mma<1024, 1, false>,
                         cudaFuncAttributeMaxDynamicSharedMemorySize, SMEM_TOT);

    prep_aw0<<<1408, 256>>>(x, emb, W0);

    dim3 g0(64, 17);   // y==16 blocks convert W1 under cover of the L0 GEMM
    lstm_mma<512, 0, true><<<g0, 256, SMEM_TOT>>>(bi0, bh0, W1, out);
    dim3 g1(64, 16);
    lstm_mma<1024, 1, false><<<g1, 256, SMEM_TOT>>>(bi1, bh1, nullptr, out);
}